// round 7
// baseline (speedup 1.0000x reference)
#include <cuda_runtime.h>

// QModel_43885975830736 — FINAL (converged; R3/R5/R6 identical binary,
// measured 4.83 / 5.02 / 4.58 us — pure noise band around ~4.8us).
//
// Math identity (rel_err 3.07e-7, bit-stable across 6 runs): wire 8 is never
// acted on by any gate, so its |1> amplitude block remains exactly zero;
// all gates are unitary and the embedding is normalized, hence
// probs(wire 8) == [1, 0] for every batch row, independent of x and weights.
// The entire workload reduces to writing the 1,0,1,0,... pattern (128 KB).
//
// Perf: pinned at the graph-replay launch-overhead floor. Kernel dur
// 3.33-3.46us across runs with DRAM 0.0% — store traffic is invisible.
// Probed axes (all worse or noise): more blocks (R2 +0.2us), fatter threads
// (R4 +0.6us, regs 16->38), v4 vs v8 (noise), multi-node graph variants
// (rejected: strictly more dispatch). Optimum: single wave, 16 blocks x 256
// threads, one 256-bit store per thread, 16 regs, one pointer param.

__global__ void __launch_bounds__(256, 1)
qmodel_fill8(float* __restrict__ out) {
    unsigned idx = blockIdx.x * 256u + threadIdx.x;
    float* p = out + (size_t)idx * 8u;
    asm volatile(
        "st.global.v8.f32 [%0], {%1, %2, %1, %2, %1, %2, %1, %2};"
        :: "l"(p), "f"(1.0f), "f"(0.0f)
        : "memory");
}

// Guarded fallback for any unexpected out_size.
__global__ void __launch_bounds__(256, 1)
qmodel_fill_guarded(float* __restrict__ out, int n) {
    int i = blockIdx.x * 256 + threadIdx.x;
    if (i < n) out[i] = (i & 1) ? 0.0f : 1.0f;
}

extern "C" void kernel_launch(void* const* d_in, const int* in_sizes, int n_in,
                              void* d_out, int out_size) {
    (void)d_in; (void)in_sizes; (void)n_in;
    if ((out_size & 2047) == 0 && out_size > 0) {
        int threads_total = out_size >> 3;   // one v8 store each
        int blocks = threads_total >> 8;     // /256, exact by the mask check
        qmodel_fill8<<<blocks, 256>>>((float*)d_out);
        return;
    }
    int blocks = (out_size + 255) / 256;
    if (blocks < 1) blocks = 1;
    qmodel_fill_guarded<<<blocks, 256>>>((float*)d_out, out_size);
}

// round 8
// speedup vs baseline: 1.1329x; 1.1329x over previous
#include <cuda_runtime.h>

// QModel_43885975830736 — constant-output identity (rel_err 3.07e-7,
// bit-stable across 7 runs): wire 8 is never acted on by any gate, so its
// |1> amplitude block remains exactly zero; gates are unitary and the
// embedding is normalized, hence probs(wire 8) == [1, 0] for every batch
// row. The workload reduces to writing 1,0,1,0,... (128 KB).
//
// Perf state: launch-overhead floor. Identical-binary runs of the 16x256
// shape: dur_us {4.58, 4.83, 5.02, 5.18}, kernel {3.33-3.46us}. This round
// probes the last untested axis: block count at constant one-store-per-
// thread shape — 4 blocks x 1024 threads (same 4096 independent v8 stores,
// 4 CTAs to dispatch instead of 16).

__global__ void __launch_bounds__(1024, 1)
qmodel_fill8_fat(float* __restrict__ out) {
    unsigned idx = blockIdx.x * 1024u + threadIdx.x;
    float* p = out + (size_t)idx * 8u;
    asm volatile(
        "st.global.v8.f32 [%0], {%1, %2, %1, %2, %1, %2, %1, %2};"
        :: "l"(p), "f"(1.0f), "f"(0.0f)
        : "memory");
}

// Guarded fallback for any unexpected out_size.
__global__ void __launch_bounds__(256, 1)
qmodel_fill_guarded(float* __restrict__ out, int n) {
    int i = blockIdx.x * 256 + threadIdx.x;
    if (i < n) out[i] = (i & 1) ? 0.0f : 1.0f;
}

extern "C" void kernel_launch(void* const* d_in, const int* in_sizes, int n_in,
                              void* d_out, int out_size) {
    (void)d_in; (void)in_sizes; (void)n_in;
    if ((out_size & 8191) == 0 && out_size > 0) {
        int threads_total = out_size >> 3;    // one v8 store each (4096)
        int blocks = threads_total >> 10;     // /1024, exact by the mask check
        qmodel_fill8_fat<<<blocks, 1024>>>((float*)d_out);
        return;
    }
    int blocks = (out_size + 255) / 256;
    if (blocks < 1) blocks = 1;
    qmodel_fill_guarded<<<blocks, 256>>>((float*)d_out, out_size);
}